// round 5
// baseline (speedup 1.0000x reference)
#include <cuda_runtime.h>
#include <math.h>

#define NN    50000
#define FIN   512
#define HEADS 4
#define HID   64
#define NCLS  40
#define EE    800000
#define ETOT  (EE + NN)      // 850000 (with self loops)
#define D1    (HEADS * HID)  // 256

// ---------------- scratch (device globals; no allocation allowed) ----------
static __device__ float g_h  [(size_t)NN * D1];      // GEMM output h
static __device__ float g_buf[(size_t)NN * D1];      // aggregated output / next input
static __device__ float g_e  [(size_t)ETOT * HEADS]; // unnormalized alpha, CSR order
static __device__ float g_as [NN * HEADS];
static __device__ float g_ad [NN * HEADS];
static __device__ float g_r  [NN * HEADS];           // 1/denominator per node,head
static __device__ int   g_deg[NN];
static __device__ int   g_off[NN + 1];
static __device__ int   g_cur[NN];
static __device__ int   g_srcs[ETOT];                // src node ids grouped by dst

// ---------------- tf32 helpers ---------------------------------------------
__device__ __forceinline__ unsigned f2tf(float f) {
    unsigned u;
    asm("cvt.rna.tf32.f32 %0, %1;" : "=r"(u) : "f"(f));
    return u;
}
__device__ __forceinline__ uint2 split2(float f) {
    unsigned hi = f2tf(f);
    float r = f - __uint_as_float(hi);
    return make_uint2(hi, f2tf(r));
}
__device__ __forceinline__ void mma_tf32(float c[4],
                                         unsigned a0, unsigned a1, unsigned a2, unsigned a3,
                                         unsigned b0, unsigned b1) {
    asm volatile(
        "mma.sync.aligned.m16n8k8.row.col.f32.tf32.tf32.f32 "
        "{%0,%1,%2,%3}, {%4,%5,%6,%7}, {%8,%9}, {%0,%1,%2,%3};"
        : "+f"(c[0]), "+f"(c[1]), "+f"(c[2]), "+f"(c[3])
        : "r"(a0), "r"(a1), "r"(a2), "r"(a3), "r"(b0), "r"(b1));
}

// ---------------- GEMM: C[M,N] = A[M,K] @ W[K,N], 3xTF32 tensor cores ------
// 128x128 block tile, BK=16, 8 warps (2m x 4n), warp tile 64x32.
// Smem holds pre-split (hi,lo) tf32 pairs as uint2; inner loop is LDS.64+MMA.
// Register-prefetch pipeline hides global-load latency behind MMA work.
#define BK  16
#define SAU 132   // uint2 stride: 2*132 mod 32 == 8 -> conflict-free frag loads
__global__ __launch_bounds__(256) void gemm_tf32(const float* __restrict__ A,
                                                 const float* __restrict__ W,
                                                 float* __restrict__ C,
                                                 int M, int N, int K) {
    __shared__ uint2 As2[BK][SAU];   // [k][m] (hi,lo)
    __shared__ uint2 Bs2[BK][SAU];   // [k][n] (hi,lo)

    int tid  = threadIdx.x;
    int lane = tid & 31;
    int wid  = tid >> 5;
    int warpM = wid & 1;
    int warpN = wid >> 1;
    int g = lane >> 2, t = lane & 3;

    int bm = blockIdx.x * 128;
    int bn = blockIdx.y * 128;

    float acc[4][4][4];
#pragma unroll
    for (int i = 0; i < 4; i++)
#pragma unroll
        for (int j = 0; j < 4; j++)
#pragma unroll
            for (int q = 0; q < 4; q++) acc[i][j][q] = 0.f;

    // loader mapping
    int ar  = tid >> 1;            // 0..127 : A row (m) within tile
    int ak8 = (tid & 1) * 8;       // 0/8    : A k base (8 consecutive k)
    int bkr = tid >> 4;            // 0..15  : B k row
    int bc8 = (tid & 15) * 8;      // 0..120 : B col base (8 consecutive n)
    int arow = bm + ar;
    bool aok  = arow < M;
    bool bok0 = bn + bc8 + 3 < N;
    bool bok1 = bn + bc8 + 7 < N;
    const float* aptr = A + (size_t)(aok ? arow : 0) * K + ak8;
    const float* bptr = W + (size_t)bkr * N + bn + bc8;

    float4 aR0, aR1, bR0, bR1;
    const float4 Z = make_float4(0.f, 0.f, 0.f, 0.f);

    // prologue: load tile 0
    aR0 = aok  ? *(const float4*)(aptr)     : Z;
    aR1 = aok  ? *(const float4*)(aptr + 4) : Z;
    bR0 = bok0 ? *(const float4*)(bptr)     : Z;
    bR1 = bok1 ? *(const float4*)(bptr + 4) : Z;

    int rowb = warpM * 64 + g;
    int colb = warpN * 32 + g;

    for (int k0 = 0;; ) {
        // split + store current tile to smem
        As2[ak8 + 0][ar] = split2(aR0.x);
        As2[ak8 + 1][ar] = split2(aR0.y);
        As2[ak8 + 2][ar] = split2(aR0.z);
        As2[ak8 + 3][ar] = split2(aR0.w);
        As2[ak8 + 4][ar] = split2(aR1.x);
        As2[ak8 + 5][ar] = split2(aR1.y);
        As2[ak8 + 6][ar] = split2(aR1.z);
        As2[ak8 + 7][ar] = split2(aR1.w);
        Bs2[bkr][bc8 + 0] = split2(bR0.x);
        Bs2[bkr][bc8 + 1] = split2(bR0.y);
        Bs2[bkr][bc8 + 2] = split2(bR0.z);
        Bs2[bkr][bc8 + 3] = split2(bR0.w);
        Bs2[bkr][bc8 + 4] = split2(bR1.x);
        Bs2[bkr][bc8 + 5] = split2(bR1.y);
        Bs2[bkr][bc8 + 6] = split2(bR1.z);
        Bs2[bkr][bc8 + 7] = split2(bR1.w);
        __syncthreads();

        bool last = (k0 + BK >= K);
        if (!last) {
            // prefetch next tile into registers (LDG overlaps MMA below)
            const float* ap = aptr + k0 + BK;
            const float* bp = bptr + (size_t)(k0 + BK) * N;
            aR0 = aok  ? *(const float4*)(ap)     : Z;
            aR1 = aok  ? *(const float4*)(ap + 4) : Z;
            bR0 = bok0 ? *(const float4*)(bp)     : Z;
            bR1 = bok1 ? *(const float4*)(bp + 4) : Z;
        }

#pragma unroll
        for (int kk = 0; kk < BK; kk += 8) {
            uint2 aF[4][4], bF[4][2];
#pragma unroll
            for (int mt = 0; mt < 4; mt++) {
                int r = rowb + mt * 16;
                aF[mt][0] = As2[kk + t    ][r    ];
                aF[mt][1] = As2[kk + t    ][r + 8];
                aF[mt][2] = As2[kk + t + 4][r    ];
                aF[mt][3] = As2[kk + t + 4][r + 8];
            }
#pragma unroll
            for (int nt = 0; nt < 4; nt++) {
                int c = colb + nt * 8;
                bF[nt][0] = Bs2[kk + t    ][c];
                bF[nt][1] = Bs2[kk + t + 4][c];
            }
#pragma unroll
            for (int mt = 0; mt < 4; mt++)
#pragma unroll
                for (int nt = 0; nt < 4; nt++) {
                    mma_tf32(acc[mt][nt],
                             aF[mt][0].x, aF[mt][1].x, aF[mt][2].x, aF[mt][3].x,
                             bF[nt][0].y, bF[nt][1].y);
                    mma_tf32(acc[mt][nt],
                             aF[mt][0].y, aF[mt][1].y, aF[mt][2].y, aF[mt][3].y,
                             bF[nt][0].x, bF[nt][1].x);
                    mma_tf32(acc[mt][nt],
                             aF[mt][0].x, aF[mt][1].x, aF[mt][2].x, aF[mt][3].x,
                             bF[nt][0].x, bF[nt][1].x);
                }
        }
        if (last) break;
        __syncthreads();
        k0 += BK;
    }

    // store C
#pragma unroll
    for (int mt = 0; mt < 4; mt++) {
        int row0 = bm + warpM * 64 + mt * 16 + g;
#pragma unroll
        for (int nt = 0; nt < 4; nt++) {
            int col = bn + warpN * 32 + nt * 8 + 2 * t;
            if (col < N) {
                if (row0 < M)
                    *(float2*)&C[(size_t)row0 * N + col] =
                        make_float2(acc[mt][nt][0], acc[mt][nt][1]);
                if (row0 + 8 < M)
                    *(float2*)&C[(size_t)(row0 + 8) * N + col] =
                        make_float2(acc[mt][nt][2], acc[mt][nt][3]);
            }
        }
    }
}

// ---------------- CSR build --------------------------------------------------
__global__ void k_zero_deg() {
    int i = blockIdx.x * blockDim.x + threadIdx.x;
    if (i < NN) g_deg[i] = 0;
}

__global__ void k_count(const int* __restrict__ ei) {
    int e = blockIdx.x * blockDim.x + threadIdx.x;
    if (e >= ETOT) return;
    int d = e < EE ? ei[EE + e] : e - EE;
    atomicAdd(&g_deg[d], 1);
}

__global__ __launch_bounds__(1024) void k_scan() {
    __shared__ int part[1024];
    const int SEG = (NN + 1023) / 1024;
    int t = threadIdx.x;
    int lo = t * SEG, hi = min(NN, lo + SEG);
    int s = 0;
    for (int i = lo; i < hi; i++) s += g_deg[i];
    part[t] = s;
    __syncthreads();
    for (int off = 1; off < 1024; off <<= 1) {
        int v = 0;
        if (t >= off) v = part[t - off];
        __syncthreads();
        if (t >= off) part[t] += v;
        __syncthreads();
    }
    int run = t ? part[t - 1] : 0;
    for (int i = lo; i < hi; i++) {
        g_off[i] = run;
        g_cur[i] = run;
        run += g_deg[i];
    }
    if (t == 0) g_off[NN] = part[1023];
}

__global__ void k_scatter(const int* __restrict__ ei) {
    int e = blockIdx.x * blockDim.x + threadIdx.x;
    if (e >= ETOT) return;
    int s, d;
    if (e < EE) { s = ei[e]; d = ei[EE + e]; }
    else        { s = d = e - EE; }
    int pos = atomicAdd(&g_cur[d], 1);
    g_srcs[pos] = s;
}

// ---------------- per-node: a_s, a_d -----------------------------------------
__global__ void node_prep(const float* __restrict__ h,
                          const float* __restrict__ atts,
                          const float* __restrict__ attd,
                          int H, int C) {
    int warp = (blockIdx.x * blockDim.x + threadIdx.x) >> 5;
    int lane = threadIdx.x & 31;
    if (warp >= NN) return;
    int HC = H * C;
    const float* hr = h + (size_t)warp * HC;
    for (int hd = 0; hd < H; hd++) {
        float s = 0.f, d = 0.f;
        for (int c = lane; c < C; c += 32) {
            float v = hr[hd * C + c];
            s += v * atts[hd * C + c];
            d += v * attd[hd * C + c];
        }
#pragma unroll
        for (int o = 16; o; o >>= 1) {
            s += __shfl_down_sync(0xFFFFFFFFu, s, o);
            d += __shfl_down_sync(0xFFFFFFFFu, d, o);
        }
        if (lane == 0) {
            g_as[warp * H + hd] = s;
            g_ad[warp * H + hd] = d;
        }
    }
}

// ---------------- softmax coefs (H=4): one warp per dst node -----------------
__global__ __launch_bounds__(256) void attn_coef4() {
    int node = (blockIdx.x * blockDim.x + threadIdx.x) >> 5;
    int lane = threadIdx.x & 31;
    if (node >= NN) return;
    int beg = g_off[node];
    int deg = g_off[node + 1] - beg;

    float4 adv = *(const float4*)&g_ad[node * 4];
    float mx0 = -1e30f, mx1 = -1e30f, mx2 = -1e30f, mx3 = -1e30f;

    float c0 = 0.f, c1 = 0.f, c2 = 0.f, c3 = 0.f;
    bool have = lane < deg;
    if (have) {
        int s = g_srcs[beg + lane];
        float4 av = *(const float4*)&g_as[s * 4];
        c0 = av.x + adv.x; c1 = av.y + adv.y;
        c2 = av.z + adv.z; c3 = av.w + adv.w;
        c0 = c0 > 0.f ? c0 : 0.2f * c0;
        c1 = c1 > 0.f ? c1 : 0.2f * c1;
        c2 = c2 > 0.f ? c2 : 0.2f * c2;
        c3 = c3 > 0.f ? c3 : 0.2f * c3;
        mx0 = c0; mx1 = c1; mx2 = c2; mx3 = c3;
    }
    for (int base = 32; base < deg; base += 32) {
        int i = base + lane;
        if (i < deg) {
            int s = g_srcs[beg + i];
            float4 av = *(const float4*)&g_as[s * 4];
            float v0 = av.x + adv.x, v1 = av.y + adv.y;
            float v2 = av.z + adv.z, v3 = av.w + adv.w;
            v0 = v0 > 0.f ? v0 : 0.2f * v0;
            v1 = v1 > 0.f ? v1 : 0.2f * v1;
            v2 = v2 > 0.f ? v2 : 0.2f * v2;
            v3 = v3 > 0.f ? v3 : 0.2f * v3;
            mx0 = fmaxf(mx0, v0); mx1 = fmaxf(mx1, v1);
            mx2 = fmaxf(mx2, v2); mx3 = fmaxf(mx3, v3);
        }
    }
#pragma unroll
    for (int o = 16; o; o >>= 1) {
        mx0 = fmaxf(mx0, __shfl_xor_sync(0xFFFFFFFFu, mx0, o));
        mx1 = fmaxf(mx1, __shfl_xor_sync(0xFFFFFFFFu, mx1, o));
        mx2 = fmaxf(mx2, __shfl_xor_sync(0xFFFFFFFFu, mx2, o));
        mx3 = fmaxf(mx3, __shfl_xor_sync(0xFFFFFFFFu, mx3, o));
    }
    float s0 = 0.f, s1 = 0.f, s2 = 0.f, s3 = 0.f;
    if (have) {
        float a0 = __expf(c0 - mx0), a1 = __expf(c1 - mx1);
        float a2 = __expf(c2 - mx2), a3 = __expf(c3 - mx3);
        *(float4*)&g_e[(size_t)(beg + lane) * 4] = make_float4(a0, a1, a2, a3);
        s0 = a0; s1 = a1; s2 = a2; s3 = a3;
    }
    for (int base = 32; base < deg; base += 32) {
        int i = base + lane;
        if (i < deg) {
            int s = g_srcs[beg + i];
            float4 av = *(const float4*)&g_as[s * 4];
            float v0 = av.x + adv.x, v1 = av.y + adv.y;
            float v2 = av.z + adv.z, v3 = av.w + adv.w;
            v0 = v0 > 0.f ? v0 : 0.2f * v0;
            v1 = v1 > 0.f ? v1 : 0.2f * v1;
            v2 = v2 > 0.f ? v2 : 0.2f * v2;
            v3 = v3 > 0.f ? v3 : 0.2f * v3;
            float a0 = __expf(v0 - mx0), a1 = __expf(v1 - mx1);
            float a2 = __expf(v2 - mx2), a3 = __expf(v3 - mx3);
            *(float4*)&g_e[(size_t)(beg + i) * 4] = make_float4(a0, a1, a2, a3);
            s0 += a0; s1 += a1; s2 += a2; s3 += a3;
        }
    }
#pragma unroll
    for (int o = 16; o; o >>= 1) {
        s0 += __shfl_xor_sync(0xFFFFFFFFu, s0, o);
        s1 += __shfl_xor_sync(0xFFFFFFFFu, s1, o);
        s2 += __shfl_xor_sync(0xFFFFFFFFu, s2, o);
        s3 += __shfl_xor_sync(0xFFFFFFFFu, s3, o);
    }
    if (lane == 0)
        *(float4*)&g_r[node * 4] = make_float4(1.f / s0, 1.f / s1, 1.f / s2, 1.f / s3);
}

// ---------------- softmax coefs (H=1) ----------------------------------------
__global__ __launch_bounds__(256) void attn_coef1() {
    int node = (blockIdx.x * blockDim.x + threadIdx.x) >> 5;
    int lane = threadIdx.x & 31;
    if (node >= NN) return;
    int beg = g_off[node];
    int deg = g_off[node + 1] - beg;

    float adv = g_ad[node];
    float vc = 0.f;
    bool have = lane < deg;
    float mx = -1e30f;
    if (have) {
        int s = g_srcs[beg + lane];
        float v = g_as[s] + adv;
        vc = v > 0.f ? v : 0.2f * v;
        mx = vc;
    }
    for (int base = 32; base < deg; base += 32) {
        int i = base + lane;
        if (i < deg) {
            int s = g_srcs[beg + i];
            float v = g_as[s] + adv;
            v = v > 0.f ? v : 0.2f * v;
            mx = fmaxf(mx, v);
        }
    }
#pragma unroll
    for (int o = 16; o; o >>= 1) mx = fmaxf(mx, __shfl_xor_sync(0xFFFFFFFFu, mx, o));
    float sm = 0.f;
    if (have) {
        float a = __expf(vc - mx);
        g_e[beg + lane] = a;
        sm = a;
    }
    for (int base = 32; base < deg; base += 32) {
        int i = base + lane;
        if (i < deg) {
            int s = g_srcs[beg + i];
            float v = g_as[s] + adv;
            v = v > 0.f ? v : 0.2f * v;
            float a = __expf(v - mx);
            g_e[beg + i] = a;
            sm += a;
        }
    }
#pragma unroll
    for (int o = 16; o; o >>= 1) sm += __shfl_xor_sync(0xFFFFFFFFu, sm, o);
    if (lane == 0) g_r[node] = 1.f / sm;
}

// ---------------- aggregation: one warp per dst node, 256 channels ----------
__global__ __launch_bounds__(256) void aggr256(const float* __restrict__ h,
                                               const float* __restrict__ bias,
                                               float* __restrict__ obuf,
                                               int apply_elu) {
    int node = (blockIdx.x * blockDim.x + threadIdx.x) >> 5;
    int lane = threadIdx.x & 31;
    if (node >= NN) return;
    int beg = g_off[node];
    int deg = g_off[node + 1] - beg;
    int c  = lane * 8;
    int hd = lane >> 3;

    float4 a0 = make_float4(0.f, 0.f, 0.f, 0.f);
    float4 a1 = make_float4(0.f, 0.f, 0.f, 0.f);

    int sp = g_srcs[beg];                    // prefetch (deg >= 1 always)
    for (int i = 0; i < deg; i++) {
        int cs = sp;
        if (i + 1 < deg) sp = g_srcs[beg + i + 1];
        float4 cf = *(const float4*)&g_e[(size_t)(beg + i) * 4];
        float coef = hd == 0 ? cf.x : hd == 1 ? cf.y : hd == 2 ? cf.z : cf.w;
        const float4* hp = (const float4*)(h + (size_t)cs * 256 + c);
        float4 v0 = hp[0], v1 = hp[1];
        a0.x += coef * v0.x; a0.y += coef * v0.y;
        a0.z += coef * v0.z; a0.w += coef * v0.w;
        a1.x += coef * v1.x; a1.y += coef * v1.y;
        a1.z += coef * v1.z; a1.w += coef * v1.w;
    }
    float4 rv = *(const float4*)&g_r[node * 4];
    float r = hd == 0 ? rv.x : hd == 1 ? rv.y : hd == 2 ? rv.z : rv.w;
    float4 b0 = *(const float4*)&bias[c];
    float4 b1 = *(const float4*)&bias[c + 4];
    a0.x = a0.x * r + b0.x; a0.y = a0.y * r + b0.y;
    a0.z = a0.z * r + b0.z; a0.w = a0.w * r + b0.w;
    a1.x = a1.x * r + b1.x; a1.y = a1.y * r + b1.y;
    a1.z = a1.z * r + b1.z; a1.w = a1.w * r + b1.w;
    if (apply_elu) {
        a0.x = a0.x > 0.f ? a0.x : expm1f(a0.x);
        a0.y = a0.y > 0.f ? a0.y : expm1f(a0.y);
        a0.z = a0.z > 0.f ? a0.z : expm1f(a0.z);
        a0.w = a0.w > 0.f ? a0.w : expm1f(a0.w);
        a1.x = a1.x > 0.f ? a1.x : expm1f(a1.x);
        a1.y = a1.y > 0.f ? a1.y : expm1f(a1.y);
        a1.z = a1.z > 0.f ? a1.z : expm1f(a1.z);
        a1.w = a1.w > 0.f ? a1.w : expm1f(a1.w);
    }
    float4* op = (float4*)(obuf + (size_t)node * 256 + c);
    op[0] = a0;
    op[1] = a1;
}

// ---------------- aggregation, layer 3: 40 channels, H=1 ---------------------
__global__ __launch_bounds__(256) void aggr40(const float* __restrict__ h,
                                              const float* __restrict__ bias,
                                              float* __restrict__ out) {
    int node = (blockIdx.x * blockDim.x + threadIdx.x) >> 5;
    int lane = threadIdx.x & 31;
    if (node >= NN) return;
    int beg = g_off[node];
    int deg = g_off[node + 1] - beg;

    float4 acc = make_float4(0.f, 0.f, 0.f, 0.f);
    int c = lane * 4;
    bool act = lane < 10;

    int sp = g_srcs[beg];
    for (int i = 0; i < deg; i++) {
        int cs = sp;
        if (i + 1 < deg) sp = g_srcs[beg + i + 1];
        float coef = g_e[beg + i];
        if (act) {
            float4 v = *(const float4*)(h + (size_t)cs * 40 + c);
            acc.x += coef * v.x; acc.y += coef * v.y;
            acc.z += coef * v.z; acc.w += coef * v.w;
        }
    }
    if (act) {
        float r = g_r[node];
        float4 b = *(const float4*)&bias[c];
        acc.x = acc.x * r + b.x; acc.y = acc.y * r + b.y;
        acc.z = acc.z * r + b.z; acc.w = acc.w * r + b.w;
        *(float4*)(out + (size_t)node * 40 + c) = acc;
    }
}

// ---------------- driver ----------------------------------------------------
extern "C" void kernel_launch(void* const* d_in, const int* in_sizes, int n_in,
                              void* d_out, int out_size) {
    const float* x   = (const float*)d_in[0];
    const int*   ei  = (const int*)  d_in[1];
    const float* W1  = (const float*)d_in[2];
    const float* as1 = (const float*)d_in[3];
    const float* ad1 = (const float*)d_in[4];
    const float* b1  = (const float*)d_in[5];
    const float* W2  = (const float*)d_in[6];
    const float* as2 = (const float*)d_in[7];
    const float* ad2 = (const float*)d_in[8];
    const float* b2  = (const float*)d_in[9];
    const float* W3  = (const float*)d_in[10];
    const float* as3 = (const float*)d_in[11];
    const float* ad3 = (const float*)d_in[12];
    const float* b3  = (const float*)d_in[13];
    float* out = (float*)d_out;

    float *h, *buf;
    cudaGetSymbolAddress((void**)&h,   g_h);
    cudaGetSymbolAddress((void**)&buf, g_buf);

    const int TB = 256;
    int gE = (ETOT + TB - 1) / TB;
    int gW = (NN * 32 + TB - 1) / TB;   // one warp per node

    // ---- CSR by dst (edge structure shared by all layers) ----
    k_zero_deg<<<(NN + TB - 1) / TB, TB>>>();
    k_count  <<<gE, TB>>>(ei);
    k_scan   <<<1, 1024>>>();
    k_scatter<<<gE, TB>>>(ei);

    // ---- layer 1 ----
    dim3 g1((NN + 127) / 128, (D1 + 127) / 128);
    gemm_tf32 <<<g1, TB>>>(x, W1, h, NN, D1, FIN);
    node_prep <<<gW, TB>>>(h, as1, ad1, HEADS, HID);
    attn_coef4<<<gW, TB>>>();
    aggr256   <<<gW, TB>>>(h, b1, buf, 1);

    // ---- layer 2 ----
    gemm_tf32 <<<g1, TB>>>(buf, W2, h, NN, D1, D1);
    node_prep <<<gW, TB>>>(h, as2, ad2, HEADS, HID);
    attn_coef4<<<gW, TB>>>();
    aggr256   <<<gW, TB>>>(h, b2, buf, 1);

    // ---- layer 3 ----
    dim3 g3((NN + 127) / 128, 1);
    gemm_tf32 <<<g3, TB>>>(buf, W3, h, NN, NCLS, D1);
    node_prep <<<gW, TB>>>(h, as3, ad3, 1, NCLS);
    attn_coef1<<<gW, TB>>>();
    aggr40    <<<gW, TB>>>(h, b3, out);
}

// round 6
// speedup vs baseline: 1.3432x; 1.3432x over previous
#include <cuda_runtime.h>
#include <math.h>

#define NN    50000
#define FIN   512
#define HEADS 4
#define HID   64
#define NCLS  40
#define EE    800000
#define ETOT  (EE + NN)      // 850000 (with self loops)
#define D1    (HEADS * HID)  // 256

// ---------------- scratch (device globals; no allocation allowed) ----------
static __device__ float g_h  [(size_t)NN * D1];      // GEMM output h
static __device__ float g_buf[(size_t)NN * D1];      // aggregated output / next input
static __device__ float g_e  [(size_t)ETOT * HEADS]; // unnormalized alpha, CSR order
static __device__ float g_as [NN * HEADS];
static __device__ float g_ad [NN * HEADS];
static __device__ float g_r  [NN * HEADS];           // 1/denominator per node,head
static __device__ int   g_deg[NN];
static __device__ int   g_off[NN + 1];
static __device__ int   g_cur[NN];
static __device__ int   g_srcs[ETOT];                // src node ids grouped by dst

// ---------------- tf32 helpers ---------------------------------------------
__device__ __forceinline__ unsigned f2tf(float f) {
    unsigned u;
    asm("cvt.rna.tf32.f32 %0, %1;" : "=r"(u) : "f"(f));
    return u;
}
__device__ __forceinline__ void tf_split(float f, unsigned& hi, unsigned& lo) {
    hi = f2tf(f);
    float r = f - __uint_as_float(hi);
    lo = f2tf(r);
}
__device__ __forceinline__ void mma_tf32(float c[4],
                                         unsigned a0, unsigned a1, unsigned a2, unsigned a3,
                                         unsigned b0, unsigned b1) {
    asm volatile(
        "mma.sync.aligned.m16n8k8.row.col.f32.tf32.tf32.f32 "
        "{%0,%1,%2,%3}, {%4,%5,%6,%7}, {%8,%9}, {%0,%1,%2,%3};"
        : "+f"(c[0]), "+f"(c[1]), "+f"(c[2]), "+f"(c[3])
        : "r"(a0), "r"(a1), "r"(a2), "r"(a3), "r"(b0), "r"(b1));
}

__device__ __forceinline__ void cp16(unsigned dst, const void* src, int srcsize) {
    asm volatile("cp.async.cg.shared.global [%0], [%1], 16, %2;"
                 :: "r"(dst), "l"(src), "r"(srcsize));
}

// ---------------- GEMM: C[M,N] = A[M,K] @ W[K,N], 3xTF32 tensor cores ------
// 128x128 block tile, BK=16, 8 warps (2m x 4n), warp tile 64x32.
// cp.async 2-stage double buffer hides global-load latency at zero register cost.
// A stored [m][k] (stride 20 -> banks 20g+t, conflict-free), B stored [k][n]
// (stride 136 -> banks 8t+g, conflict-free). Split to tf32 hi/lo in-loop (R4).
#define BK  16
#define SAK 20    // A smem k-stride (16 + 4 pad)
#define SB  136   // B smem n-stride
__global__ __launch_bounds__(256) void gemm_tf32(const float* __restrict__ A,
                                                 const float* __restrict__ W,
                                                 float* __restrict__ C,
                                                 int M, int N, int K) {
    __shared__ __align__(16) float As[2][128][SAK];
    __shared__ __align__(16) float Bs[2][BK][SB];

    int tid  = threadIdx.x;
    int lane = tid & 31;
    int wid  = tid >> 5;
    int warpM = wid & 1;
    int warpN = wid >> 1;
    int g = lane >> 2, t = lane & 3;

    int bm = blockIdx.x * 128;
    int bn = blockIdx.y * 128;

    float acc[4][4][4];
#pragma unroll
    for (int i = 0; i < 4; i++)
#pragma unroll
        for (int j = 0; j < 4; j++)
#pragma unroll
            for (int q = 0; q < 4; q++) acc[i][j][q] = 0.f;

    // loader mapping
    int ar = tid >> 1;             // 0..127 : A row within tile
    int ak = (tid & 1) * 8;        // 0/8    : A k base
    int bkr = tid >> 4;            // 0..15  : B k row
    int bc  = (tid & 15) * 8;      // 0..120 : B col base
    int arow = bm + ar; if (arow >= M) arow = M - 1;   // clamp (rows >= M not stored)
    int bs0 = (bn + bc + 3 < N) ? 16 : 0;              // zero-fill OOB columns
    int bs1 = (bn + bc + 7 < N) ? 16 : 0;
    const float* aptr = A + (size_t)arow * K + ak;
    const float* bptr = W + (size_t)bkr * N + bn + bc;

    unsigned sA = (unsigned)__cvta_generic_to_shared(&As[0][0][0]);
    unsigned sB = (unsigned)__cvta_generic_to_shared(&Bs[0][0][0]);
    unsigned dA = sA + (ar * SAK + ak) * 4;
    unsigned dB = sB + (bkr * SB + bc) * 4;
    const unsigned stA = 128 * SAK * 4;   // stage stride (bytes)
    const unsigned stB = BK * SB * 4;

    int T = K / BK;
    // prologue: tile 0 -> stage 0
    cp16(dA,      aptr,     16);
    cp16(dA + 16, aptr + 4, 16);
    cp16(dB,      bptr,     bs0);
    cp16(dB + 16, bptr + 4, bs1);
    asm volatile("cp.async.commit_group;");

    int rowb = warpM * 64 + g;
    int colb = warpN * 32 + g;

    for (int tt = 0; tt < T; tt++) {
        int cur = tt & 1;
        if (tt + 1 < T) {
            int nxt = cur ^ 1;
            const float* ap = aptr + (tt + 1) * BK;
            const float* bp = bptr + (size_t)(tt + 1) * BK * N;
            cp16(dA + nxt * stA,      ap,     16);
            cp16(dA + nxt * stA + 16, ap + 4, 16);
            cp16(dB + nxt * stB,      bp,     bs0);
            cp16(dB + nxt * stB + 16, bp + 4, bs1);
            asm volatile("cp.async.commit_group;");
            asm volatile("cp.async.wait_group 1;");
        } else {
            asm volatile("cp.async.commit_group;");
            asm volatile("cp.async.wait_group 0;");
        }
        __syncthreads();

        const float* Af = &As[cur][0][0];
        const float* Bf = &Bs[cur][0][0];
#pragma unroll
        for (int kk = 0; kk < BK; kk += 8) {
            unsigned aHi[4][4], aLo[4][4], bHi[4][2], bLo[4][2];
#pragma unroll
            for (int mt = 0; mt < 4; mt++) {
                int r = rowb + mt * 16;
                tf_split(Af[(r    ) * SAK + kk + t    ], aHi[mt][0], aLo[mt][0]);
                tf_split(Af[(r + 8) * SAK + kk + t    ], aHi[mt][1], aLo[mt][1]);
                tf_split(Af[(r    ) * SAK + kk + t + 4], aHi[mt][2], aLo[mt][2]);
                tf_split(Af[(r + 8) * SAK + kk + t + 4], aHi[mt][3], aLo[mt][3]);
            }
#pragma unroll
            for (int nt = 0; nt < 4; nt++) {
                int c = colb + nt * 8;
                tf_split(Bf[(kk + t    ) * SB + c], bHi[nt][0], bLo[nt][0]);
                tf_split(Bf[(kk + t + 4) * SB + c], bHi[nt][1], bLo[nt][1]);
            }
#pragma unroll
            for (int mt = 0; mt < 4; mt++)
#pragma unroll
                for (int nt = 0; nt < 4; nt++) {
                    mma_tf32(acc[mt][nt], aHi[mt][0], aHi[mt][1], aHi[mt][2], aHi[mt][3],
                             bLo[nt][0], bLo[nt][1]);
                    mma_tf32(acc[mt][nt], aLo[mt][0], aLo[mt][1], aLo[mt][2], aLo[mt][3],
                             bHi[nt][0], bHi[nt][1]);
                    mma_tf32(acc[mt][nt], aHi[mt][0], aHi[mt][1], aHi[mt][2], aHi[mt][3],
                             bHi[nt][0], bHi[nt][1]);
                }
        }
        __syncthreads();
    }

    // store C
#pragma unroll
    for (int mt = 0; mt < 4; mt++) {
        int row0 = bm + warpM * 64 + mt * 16 + g;
#pragma unroll
        for (int nt = 0; nt < 4; nt++) {
            int col = bn + warpN * 32 + nt * 8 + 2 * t;
            if (col < N) {
                if (row0 < M)
                    *(float2*)&C[(size_t)row0 * N + col] =
                        make_float2(acc[mt][nt][0], acc[mt][nt][1]);
                if (row0 + 8 < M)
                    *(float2*)&C[(size_t)(row0 + 8) * N + col] =
                        make_float2(acc[mt][nt][2], acc[mt][nt][3]);
            }
        }
    }
}

// ---------------- CSR build --------------------------------------------------
__global__ void k_zero_deg() {
    int i = blockIdx.x * blockDim.x + threadIdx.x;
    if (i < NN) g_deg[i] = 0;
}

__global__ void k_count(const int* __restrict__ ei) {
    int e = blockIdx.x * blockDim.x + threadIdx.x;
    if (e >= ETOT) return;
    int d = e < EE ? ei[EE + e] : e - EE;
    atomicAdd(&g_deg[d], 1);
}

__global__ __launch_bounds__(1024) void k_scan() {
    __shared__ int part[1024];
    const int SEG = (NN + 1023) / 1024;
    int t = threadIdx.x;
    int lo = t * SEG, hi = min(NN, lo + SEG);
    int s = 0;
    for (int i = lo; i < hi; i++) s += g_deg[i];
    part[t] = s;
    __syncthreads();
    for (int off = 1; off < 1024; off <<= 1) {
        int v = 0;
        if (t >= off) v = part[t - off];
        __syncthreads();
        if (t >= off) part[t] += v;
        __syncthreads();
    }
    int run = t ? part[t - 1] : 0;
    for (int i = lo; i < hi; i++) {
        g_off[i] = run;
        g_cur[i] = run;
        run += g_deg[i];
    }
    if (t == 0) g_off[NN] = part[1023];
}

__global__ void k_scatter(const int* __restrict__ ei) {
    int e = blockIdx.x * blockDim.x + threadIdx.x;
    if (e >= ETOT) return;
    int s, d;
    if (e < EE) { s = ei[e]; d = ei[EE + e]; }
    else        { s = d = e - EE; }
    int pos = atomicAdd(&g_cur[d], 1);
    g_srcs[pos] = s;
}

// ---------------- per-node: a_s, a_d -----------------------------------------
__global__ void node_prep(const float* __restrict__ h,
                          const float* __restrict__ atts,
                          const float* __restrict__ attd,
                          int H, int C) {
    int warp = (blockIdx.x * blockDim.x + threadIdx.x) >> 5;
    int lane = threadIdx.x & 31;
    if (warp >= NN) return;
    int HC = H * C;
    const float* hr = h + (size_t)warp * HC;
    for (int hd = 0; hd < H; hd++) {
        float s = 0.f, d = 0.f;
        for (int c = lane; c < C; c += 32) {
            float v = hr[hd * C + c];
            s += v * atts[hd * C + c];
            d += v * attd[hd * C + c];
        }
#pragma unroll
        for (int o = 16; o; o >>= 1) {
            s += __shfl_down_sync(0xFFFFFFFFu, s, o);
            d += __shfl_down_sync(0xFFFFFFFFu, d, o);
        }
        if (lane == 0) {
            g_as[warp * H + hd] = s;
            g_ad[warp * H + hd] = d;
        }
    }
}

// ---------------- softmax coefs (H=4): one warp per dst node -----------------
__global__ __launch_bounds__(256) void attn_coef4() {
    int node = (blockIdx.x * blockDim.x + threadIdx.x) >> 5;
    int lane = threadIdx.x & 31;
    if (node >= NN) return;
    int beg = g_off[node];
    int deg = g_off[node + 1] - beg;

    float4 adv = *(const float4*)&g_ad[node * 4];
    float mx0 = -1e30f, mx1 = -1e30f, mx2 = -1e30f, mx3 = -1e30f;

    float c0 = 0.f, c1 = 0.f, c2 = 0.f, c3 = 0.f;
    bool have = lane < deg;
    if (have) {
        int s = g_srcs[beg + lane];
        float4 av = *(const float4*)&g_as[s * 4];
        c0 = av.x + adv.x; c1 = av.y + adv.y;
        c2 = av.z + adv.z; c3 = av.w + adv.w;
        c0 = c0 > 0.f ? c0 : 0.2f * c0;
        c1 = c1 > 0.f ? c1 : 0.2f * c1;
        c2 = c2 > 0.f ? c2 : 0.2f * c2;
        c3 = c3 > 0.f ? c3 : 0.2f * c3;
        mx0 = c0; mx1 = c1; mx2 = c2; mx3 = c3;
    }
    for (int base = 32; base < deg; base += 32) {
        int i = base + lane;
        if (i < deg) {
            int s = g_srcs[beg + i];
            float4 av = *(const float4*)&g_as[s * 4];
            float v0 = av.x + adv.x, v1 = av.y + adv.y;
            float v2 = av.z + adv.z, v3 = av.w + adv.w;
            v0 = v0 > 0.f ? v0 : 0.2f * v0;
            v1 = v1 > 0.f ? v1 : 0.2f * v1;
            v2 = v2 > 0.f ? v2 : 0.2f * v2;
            v3 = v3 > 0.f ? v3 : 0.2f * v3;
            mx0 = fmaxf(mx0, v0); mx1 = fmaxf(mx1, v1);
            mx2 = fmaxf(mx2, v2); mx3 = fmaxf(mx3, v3);
        }
    }
#pragma unroll
    for (int o = 16; o; o >>= 1) {
        mx0 = fmaxf(mx0, __shfl_xor_sync(0xFFFFFFFFu, mx0, o));
        mx1 = fmaxf(mx1, __shfl_xor_sync(0xFFFFFFFFu, mx1, o));
        mx2 = fmaxf(mx2, __shfl_xor_sync(0xFFFFFFFFu, mx2, o));
        mx3 = fmaxf(mx3, __shfl_xor_sync(0xFFFFFFFFu, mx3, o));
    }
    float s0 = 0.f, s1 = 0.f, s2 = 0.f, s3 = 0.f;
    if (have) {
        float a0 = __expf(c0 - mx0), a1 = __expf(c1 - mx1);
        float a2 = __expf(c2 - mx2), a3 = __expf(c3 - mx3);
        *(float4*)&g_e[(size_t)(beg + lane) * 4] = make_float4(a0, a1, a2, a3);
        s0 = a0; s1 = a1; s2 = a2; s3 = a3;
    }
    for (int base = 32; base < deg; base += 32) {
        int i = base + lane;
        if (i < deg) {
            int s = g_srcs[beg + i];
            float4 av = *(const float4*)&g_as[s * 4];
            float v0 = av.x + adv.x, v1 = av.y + adv.y;
            float v2 = av.z + adv.z, v3 = av.w + adv.w;
            v0 = v0 > 0.f ? v0 : 0.2f * v0;
            v1 = v1 > 0.f ? v1 : 0.2f * v1;
            v2 = v2 > 0.f ? v2 : 0.2f * v2;
            v3 = v3 > 0.f ? v3 : 0.2f * v3;
            float a0 = __expf(v0 - mx0), a1 = __expf(v1 - mx1);
            float a2 = __expf(v2 - mx2), a3 = __expf(v3 - mx3);
            *(float4*)&g_e[(size_t)(beg + i) * 4] = make_float4(a0, a1, a2, a3);
            s0 += a0; s1 += a1; s2 += a2; s3 += a3;
        }
    }
#pragma unroll
    for (int o = 16; o; o >>= 1) {
        s0 += __shfl_xor_sync(0xFFFFFFFFu, s0, o);
        s1 += __shfl_xor_sync(0xFFFFFFFFu, s1, o);
        s2 += __shfl_xor_sync(0xFFFFFFFFu, s2, o);
        s3 += __shfl_xor_sync(0xFFFFFFFFu, s3, o);
    }
    if (lane == 0)
        *(float4*)&g_r[node * 4] = make_float4(1.f / s0, 1.f / s1, 1.f / s2, 1.f / s3);
}

// ---------------- softmax coefs (H=1) ----------------------------------------
__global__ __launch_bounds__(256) void attn_coef1() {
    int node = (blockIdx.x * blockDim.x + threadIdx.x) >> 5;
    int lane = threadIdx.x & 31;
    if (node >= NN) return;
    int beg = g_off[node];
    int deg = g_off[node + 1] - beg;

    float adv = g_ad[node];
    float vc = 0.f;
    bool have = lane < deg;
    float mx = -1e30f;
    if (have) {
        int s = g_srcs[beg + lane];
        float v = g_as[s] + adv;
        vc = v > 0.f ? v : 0.2f * v;
        mx = vc;
    }
    for (int base = 32; base < deg; base += 32) {
        int i = base + lane;
        if (i < deg) {
            int s = g_srcs[beg + i];
            float v = g_as[s] + adv;
            v = v > 0.f ? v : 0.2f * v;
            mx = fmaxf(mx, v);
        }
    }
#pragma unroll
    for (int o = 16; o; o >>= 1) mx = fmaxf(mx, __shfl_xor_sync(0xFFFFFFFFu, mx, o));
    float sm = 0.f;
    if (have) {
        float a = __expf(vc - mx);
        g_e[beg + lane] = a;
        sm = a;
    }
    for (int base = 32; base < deg; base += 32) {
        int i = base + lane;
        if (i < deg) {
            int s = g_srcs[beg + i];
            float v = g_as[s] + adv;
            v = v > 0.f ? v : 0.2f * v;
            float a = __expf(v - mx);
            g_e[beg + i] = a;
            sm += a;
        }
    }
#pragma unroll
    for (int o = 16; o; o >>= 1) sm += __shfl_xor_sync(0xFFFFFFFFu, sm, o);
    if (lane == 0) g_r[node] = 1.f / sm;
}

// ---------------- aggregation: one warp per dst node, 256 channels ----------
__global__ __launch_bounds__(256) void aggr256(const float* __restrict__ h,
                                               const float* __restrict__ bias,
                                               float* __restrict__ obuf,
                                               int apply_elu) {
    int node = (blockIdx.x * blockDim.x + threadIdx.x) >> 5;
    int lane = threadIdx.x & 31;
    if (node >= NN) return;
    int beg = g_off[node];
    int deg = g_off[node + 1] - beg;
    int c  = lane * 8;
    int hd = lane >> 3;

    float4 a0 = make_float4(0.f, 0.f, 0.f, 0.f);
    float4 a1 = make_float4(0.f, 0.f, 0.f, 0.f);

    int sp = g_srcs[beg];                    // prefetch (deg >= 1 always)
    for (int i = 0; i < deg; i++) {
        int cs = sp;
        if (i + 1 < deg) sp = g_srcs[beg + i + 1];
        float4 cf = *(const float4*)&g_e[(size_t)(beg + i) * 4];
        float coef = hd == 0 ? cf.x : hd == 1 ? cf.y : hd == 2 ? cf.z : cf.w;
        const float4* hp = (const float4*)(h + (size_t)cs * 256 + c);
        float4 v0 = hp[0], v1 = hp[1];
        a0.x += coef * v0.x; a0.y += coef * v0.y;
        a0.z += coef * v0.z; a0.w += coef * v0.w;
        a1.x += coef * v1.x; a1.y += coef * v1.y;
        a1.z += coef * v1.z; a1.w += coef * v1.w;
    }
    float4 rv = *(const float4*)&g_r[node * 4];
    float r = hd == 0 ? rv.x : hd == 1 ? rv.y : hd == 2 ? rv.z : rv.w;
    float4 b0 = *(const float4*)&bias[c];
    float4 b1 = *(const float4*)&bias[c + 4];
    a0.x = a0.x * r + b0.x; a0.y = a0.y * r + b0.y;
    a0.z = a0.z * r + b0.z; a0.w = a0.w * r + b0.w;
    a1.x = a1.x * r + b1.x; a1.y = a1.y * r + b1.y;
    a1.z = a1.z * r + b1.z; a1.w = a1.w * r + b1.w;
    if (apply_elu) {
        a0.x = a0.x > 0.f ? a0.x : expm1f(a0.x);
        a0.y = a0.y > 0.f ? a0.y : expm1f(a0.y);
        a0.z = a0.z > 0.f ? a0.z : expm1f(a0.z);
        a0.w = a0.w > 0.f ? a0.w : expm1f(a0.w);
        a1.x = a1.x > 0.f ? a1.x : expm1f(a1.x);
        a1.y = a1.y > 0.f ? a1.y : expm1f(a1.y);
        a1.z = a1.z > 0.f ? a1.z : expm1f(a1.z);
        a1.w = a1.w > 0.f ? a1.w : expm1f(a1.w);
    }
    float4* op = (float4*)(obuf + (size_t)node * 256 + c);
    op[0] = a0;
    op[1] = a1;
}

// ---------------- aggregation, layer 3: 40 channels, H=1 ---------------------
__global__ __launch_bounds__(256) void aggr40(const float* __restrict__ h,
                                              const float* __restrict__ bias,
                                              float* __restrict__ out) {
    int node = (blockIdx.x * blockDim.x + threadIdx.x) >> 5;
    int lane = threadIdx.x & 31;
    if (node >= NN) return;
    int beg = g_off[node];
    int deg = g_off[node + 1] - beg;

    float4 acc = make_float4(0.f, 0.f, 0.f, 0.f);
    int c = lane * 4;
    bool act = lane < 10;

    int sp = g_srcs[beg];
    for (int i = 0; i < deg; i++) {
        int cs = sp;
        if (i + 1 < deg) sp = g_srcs[beg + i + 1];
        float coef = g_e[beg + i];
        if (act) {
            float4 v = *(const float4*)(h + (size_t)cs * 40 + c);
            acc.x += coef * v.x; acc.y += coef * v.y;
            acc.z += coef * v.z; acc.w += coef * v.w;
        }
    }
    if (act) {
        float r = g_r[node];
        float4 b = *(const float4*)&bias[c];
        acc.x = acc.x * r + b.x; acc.y = acc.y * r + b.y;
        acc.z = acc.z * r + b.z; acc.w = acc.w * r + b.w;
        *(float4*)(out + (size_t)node * 40 + c) = acc;
    }
}

// ---------------- driver ----------------------------------------------------
extern "C" void kernel_launch(void* const* d_in, const int* in_sizes, int n_in,
                              void* d_out, int out_size) {
    const float* x   = (const float*)d_in[0];
    const int*   ei  = (const int*)  d_in[1];
    const float* W1  = (const float*)d_in[2];
    const float* as1 = (const float*)d_in[3];
    const float* ad1 = (const float*)d_in[4];
    const float* b1  = (const float*)d_in[5];
    const float* W2  = (const float*)d_in[6];
    const float* as2 = (const float*)d_in[7];
    const float* ad2 = (const float*)d_in[8];
    const float* b2  = (const float*)d_in[9];
    const float* W3  = (const float*)d_in[10];
    const float* as3 = (const float*)d_in[11];
    const float* ad3 = (const float*)d_in[12];
    const float* b3  = (const float*)d_in[13];
    float* out = (float*)d_out;

    float *h, *buf;
    cudaGetSymbolAddress((void**)&h,   g_h);
    cudaGetSymbolAddress((void**)&buf, g_buf);

    const int TB = 256;
    int gE = (ETOT + TB - 1) / TB;
    int gW = (NN * 32 + TB - 1) / TB;   // one warp per node

    // ---- CSR by dst (edge structure shared by all layers) ----
    k_zero_deg<<<(NN + TB - 1) / TB, TB>>>();
    k_count  <<<gE, TB>>>(ei);
    k_scan   <<<1, 1024>>>();
    k_scatter<<<gE, TB>>>(ei);

    // ---- layer 1 ----
    dim3 g1((NN + 127) / 128, (D1 + 127) / 128);
    gemm_tf32 <<<g1, TB>>>(x, W1, h, NN, D1, FIN);
    node_prep <<<gW, TB>>>(h, as1, ad1, HEADS, HID);
    attn_coef4<<<gW, TB>>>();
    aggr256   <<<gW, TB>>>(h, b1, buf, 1);

    // ---- layer 2 ----
    gemm_tf32 <<<g1, TB>>>(buf, W2, h, NN, D1, D1);
    node_prep <<<gW, TB>>>(h, as2, ad2, HEADS, HID);
    attn_coef4<<<gW, TB>>>();
    aggr256   <<<gW, TB>>>(h, b2, buf, 1);

    // ---- layer 3 ----
    dim3 g3((NN + 127) / 128, 1);
    gemm_tf32 <<<g3, TB>>>(buf, W3, h, NN, NCLS, D1);
    node_prep <<<gW, TB>>>(h, as3, ad3, 1, NCLS);
    attn_coef1<<<gW, TB>>>();
    aggr40    <<<gW, TB>>>(h, b3, out);
}